// round 15
// baseline (speedup 1.0000x reference)
#include <cuda_runtime.h>
#include <cstdint>

// Shapes (fixed):
//   z:     [16, 128, 32, 32] f32   (B=16, C=128=L*D, H=W=32)
//   codes: [8, 512, 16]      f32   (L=8, K=512, D=16)
// d_out (f32): soft[16384*128] | hard[16384*128] | idx[16384*8]

#define KN   512
#define DN   16
#define LN   8
#define NPOS 16384
#define HN   (NPOS * 128)
#define BLKPOS 222               // positions per block (74 blocks/l)

typedef unsigned long long f2;  // packed f32x2

__device__ __forceinline__ f2 pack2(float lo, float hi) {
    f2 r; asm("mov.b64 %0, {%1,%2};" : "=l"(r) : "f"(lo), "f"(hi)); return r;
}
__device__ __forceinline__ void unpack2(f2 v, float& lo, float& hi) {
    asm("mov.b64 {%0,%1}, %2;" : "=f"(lo), "=f"(hi) : "l"(v));
}
__device__ __forceinline__ f2 fma2(f2 a, f2 b, f2 c) {
    f2 d; asm("fma.rn.f32x2 %0, %1, %2, %3;" : "=l"(d) : "l"(a), "l"(b), "l"(c)); return d;
}
__device__ __forceinline__ float sqrt_approx(float x) {
    float r; asm("sqrt.approx.f32 %0, %1;" : "=f"(r) : "f"(x)); return r;
}
__device__ __forceinline__ float expneg_approx(float x) {   // e^{-x}
    float r;
    asm("mul.f32 %0, %1, 0fBFB8AA3B;\n\tex2.approx.f32 %0, %0;" : "=f"(r) : "f"(x));
    return r;
}

// exact d2 in reference order (rescan path only)
__device__ __forceinline__ float d2_exact(const float* __restrict__ h, float h2,
                                          const float* __restrict__ c, float w2) {
    float dot = 0.f;
    #pragma unroll
    for (int d = 0; d < DN; d++) dot = fmaf(h[d], c[d], dot);
    float t = fmaf(-2.0f, dot, h2);   // == fl(h2 - fl(2*dot)), 2*dot exact
    return __fadd_rn(t, w2);
}

__device__ __forceinline__ void finish_pos(
    const float* __restrict__ h, float h2, float best0, float best1, int k0,
    float S, const f2* __restrict__ acc, int n, int l,
    const float* __restrict__ cs, const float* __restrict__ w2s,
    float* __restrict__ out, int out_size)
{
    float sq0 = __fsqrt_rn(fmaxf(best0, 1e-12f));
    float sq1 = __fsqrt_rn(fmaxf(best1, 1e-12f));
    int bk = k0;
    if (sq1 == sq0) {   // plateau tie (rare): exact first-index rule
        for (int k = 0; k < KN; k++) {
            float d2 = d2_exact(h, h2, cs + k * DN, w2s[k]);
            if (__fsqrt_rn(fmaxf(d2, 1e-12f)) == sq0) { bk = k; break; }
        }
    }

    float inv = 1.0f / S;
    float so[DN];
    #pragma unroll
    for (int i = 0; i < 8; i++) unpack2(acc[i], so[2 * i], so[2 * i + 1]);

    float4* o4 = reinterpret_cast<float4*>(out + (size_t)n * 128 + l * DN);
    #pragma unroll
    for (int j = 0; j < 4; j++) {
        float4 v;
        v.x = so[4 * j + 0] * inv;
        v.y = so[4 * j + 1] * inv;
        v.z = so[4 * j + 2] * inv;
        v.w = so[4 * j + 3] * inv;
        o4[j] = v;
    }
    if (out_size >= 2 * HN) {
        const float4* cr = reinterpret_cast<const float4*>(cs + bk * DN);
        float4* ho = reinterpret_cast<float4*>(out + HN + (size_t)n * 128 + l * DN);
        #pragma unroll
        for (int j = 0; j < 4; j++) ho[j] = cr[j];
    }
    if (out_size >= 2 * HN + NPOS * LN) {
        out[2 * HN + (size_t)n * LN + l] = (float)bk;
    }
}

template<bool DO_B>
__device__ __forceinline__ void vq_work(
    int n0, int n1, bool bvalid, int l,
    const float* __restrict__ z,
    const float* __restrict__ cs, const float* __restrict__ w2s,
    float* __restrict__ out, int out_size)
{
    const int n1c = bvalid ? n1 : n0;   // safe index for loads

    float hA[DN], hB[DN];
    {
        const int b0 = n0 >> 10,  s0 = n0 & 1023;
        const float* za = z + (size_t)b0 * (128 * 1024) + (size_t)(l * DN) * 1024 + s0;
        #pragma unroll
        for (int d = 0; d < DN; d++) hA[d] = za[(size_t)d * 1024];
        if (DO_B) {
            const int b1 = n1c >> 10, s1 = n1c & 1023;
            const float* zb = z + (size_t)b1 * (128 * 1024) + (size_t)(l * DN) * 1024 + s1;
            #pragma unroll
            for (int d = 0; d < DN; d++) hB[d] = zb[(size_t)d * 1024];
        }
    }
    float h2A = 0.f, h2B = 0.f;
    #pragma unroll
    for (int d = 0; d < DN; d++) h2A = __fadd_rn(h2A, __fmul_rn(hA[d], hA[d]));
    if (DO_B) {
        #pragma unroll
        for (int d = 0; d < DN; d++) h2B = __fadd_rn(h2B, __fmul_rn(hB[d], hB[d]));
    }

    float bA0 = 3.4e38f, bA1 = 3.4e38f, bB0 = 3.4e38f, bB1 = 3.4e38f;
    int   kA0 = 0, kB0 = 0;
    float SA = 0.f, SB = 0.f;
    f2 accA[8], accB[8];
    #pragma unroll
    for (int i = 0; i < 8; i++) { accA[i] = 0ull; accB[i] = 0ull; }

    const float4*     q4 = reinterpret_cast<const float4*>(cs);      // scalar view
    const ulonglong2* qp = reinterpret_cast<const ulonglong2*>(cs);  // packed view

    #pragma unroll 4
    for (int k = 0; k < KN; k++) {
        // scalar view: feeds the exact sequential dots (no unpack movs)
        float4 qa = q4[k * 4 + 0];
        float4 qb = q4[k * 4 + 1];
        float4 qc = q4[k * 4 + 2];
        float4 qd = q4[k * 4 + 3];
        // packed view: feeds the f32x2 accumulators (no pack movs)
        ulonglong2 A = qp[k * 4 + 0];
        ulonglong2 B = qp[k * 4 + 1];
        ulonglong2 C = qp[k * 4 + 2];
        ulonglong2 D = qp[k * 4 + 3];
        float w2 = w2s[k];

        // exact sequential dots (reference contraction order)
        float dA = 0.f, dB = 0.f;
        dA = fmaf(hA[0], qa.x,dA);  if (DO_B) dB = fmaf(hB[0], qa.x,dB);
        dA = fmaf(hA[1], qa.y,dA);  if (DO_B) dB = fmaf(hB[1], qa.y,dB);
        dA = fmaf(hA[2], qa.z,dA);  if (DO_B) dB = fmaf(hB[2], qa.z,dB);
        dA = fmaf(hA[3], qa.w,dA);  if (DO_B) dB = fmaf(hB[3], qa.w,dB);
        dA = fmaf(hA[4], qb.x,dA);  if (DO_B) dB = fmaf(hB[4], qb.x,dB);
        dA = fmaf(hA[5], qb.y,dA);  if (DO_B) dB = fmaf(hB[5], qb.y,dB);
        dA = fmaf(hA[6], qb.z,dA);  if (DO_B) dB = fmaf(hB[6], qb.z,dB);
        dA = fmaf(hA[7], qb.w,dA);  if (DO_B) dB = fmaf(hB[7], qb.w,dB);
        dA = fmaf(hA[8], qc.x,dA);  if (DO_B) dB = fmaf(hB[8], qc.x,dB);
        dA = fmaf(hA[9], qc.y,dA);  if (DO_B) dB = fmaf(hB[9], qc.y,dB);
        dA = fmaf(hA[10],qc.z,dA);  if (DO_B) dB = fmaf(hB[10],qc.z,dB);
        dA = fmaf(hA[11],qc.w,dA);  if (DO_B) dB = fmaf(hB[11],qc.w,dB);
        dA = fmaf(hA[12],qd.x,dA);  if (DO_B) dB = fmaf(hB[12],qd.x,dB);
        dA = fmaf(hA[13],qd.y,dA);  if (DO_B) dB = fmaf(hB[13],qd.y,dB);
        dA = fmaf(hA[14],qd.z,dA);  if (DO_B) dB = fmaf(hB[14],qd.z,dB);
        dA = fmaf(hA[15],qd.w,dA);  if (DO_B) dB = fmaf(hB[15],qd.w,dB);

        float d2A = __fadd_rn(fmaf(-2.0f, dA, h2A), w2);

        float oA = bA0; bool lA = d2A < bA0;
        bA0 = lA ? d2A : bA0;  kA0 = lA ? k : kA0;
        bA1 = fminf(bA1, fmaxf(oA, d2A));

        float wA = expneg_approx(sqrt_approx(fmaxf(d2A, 1e-12f)));
        SA += wA;
        f2 wpA = pack2(wA, wA);
        accA[0] = fma2(wpA, A.x, accA[0]);
        accA[1] = fma2(wpA, A.y, accA[1]);
        accA[2] = fma2(wpA, B.x, accA[2]);
        accA[3] = fma2(wpA, B.y, accA[3]);
        accA[4] = fma2(wpA, C.x, accA[4]);
        accA[5] = fma2(wpA, C.y, accA[5]);
        accA[6] = fma2(wpA, D.x, accA[6]);
        accA[7] = fma2(wpA, D.y, accA[7]);

        if (DO_B) {
            float d2B = __fadd_rn(fmaf(-2.0f, dB, h2B), w2);

            float oB = bB0; bool lB = d2B < bB0;
            bB0 = lB ? d2B : bB0;  kB0 = lB ? k : kB0;
            bB1 = fminf(bB1, fmaxf(oB, d2B));

            float wB = expneg_approx(sqrt_approx(fmaxf(d2B, 1e-12f)));
            SB += wB;
            f2 wpB = pack2(wB, wB);
            accB[0] = fma2(wpB, A.x, accB[0]);
            accB[1] = fma2(wpB, A.y, accB[1]);
            accB[2] = fma2(wpB, B.x, accB[2]);
            accB[3] = fma2(wpB, B.y, accB[3]);
            accB[4] = fma2(wpB, C.x, accB[4]);
            accB[5] = fma2(wpB, C.y, accB[5]);
            accB[6] = fma2(wpB, D.x, accB[6]);
            accB[7] = fma2(wpB, D.y, accB[7]);
        }
    }

    finish_pos(hA, h2A, bA0, bA1, kA0, SA, accA, n0, l, cs, w2s, out, out_size);
    if (DO_B && bvalid)
        finish_pos(hB, h2B, bB0, bB1, kB0, SB, accB, n1, l, cs, w2s, out, out_size);
}

__global__ __launch_bounds__(128, 4)
void vq_kernel(const float* __restrict__ z,
               const float* __restrict__ codes,
               float* __restrict__ out,
               int out_size)
{
    __shared__ __align__(16) float cs[KN * DN];   // codes[l], [k][d], 32 KB
    __shared__ float w2s[KN];                     // ||codes[l][k]||^2 (ref order)

    const int l = blockIdx.y;
    const int t = threadIdx.x;

    // ---- cooperative load of codes[l] ----
    {
        const float4* cg = reinterpret_cast<const float4*>(codes + (size_t)l * KN * DN);
        float4* cs4 = reinterpret_cast<float4*>(cs);
        #pragma unroll 4
        for (int i = t; i < KN * DN / 4; i += 128) cs4[i] = cg[i];
    }
    __syncthreads();
    for (int k = t; k < KN; k += 128) {
        const float* c = cs + k * DN;
        float a = 0.f;
        #pragma unroll
        for (int d = 0; d < DN; d++) a = __fadd_rn(a, __fmul_rn(c[d], c[d]));
        w2s[k] = a;
    }
    __syncthreads();

    const int base = blockIdx.x * BLKPOS;
    const int n0 = base + t;             // always < NPOS (max 16333)
    const int n1 = base + 128 + t;       // stream B: valid iff t<94 && n1<NPOS
    const bool bvalid = (t < 94) && (n1 < NPOS);

    if (t < 96) {   // warps 0-2: dual stream
        vq_work<true>(n0, n1, bvalid, l, z, cs, w2s, out, out_size);
    } else {        // warp 3: single stream
        vq_work<false>(n0, 0, false, l, z, cs, w2s, out, out_size);
    }
}

extern "C" void kernel_launch(void* const* d_in, const int* in_sizes, int n_in,
                              void* d_out, int out_size) {
    const float* z     = (const float*)d_in[0];
    const float* codes = (const float*)d_in[1];
    float* out = (float*)d_out;

    dim3 grid(74, LN);   // 592 blocks = 148 SMs x 4 CTAs, perfectly balanced
    vq_kernel<<<grid, 128>>>(z, codes, out, out_size);
}

// round 16
// speedup vs baseline: 1.1105x; 1.1105x over previous
#include <cuda_runtime.h>
#include <cstdint>

#define KN   512
#define LN   8
#define NPOS 16384
#define HN   (NPOS * 128)
#define GUARD 2e-3f
typedef unsigned int uint;

__device__ __forceinline__ uint s2u(const void* p) {
    uint a; asm("{ .reg .u64 t; cvta.to.shared.u64 t, %1; cvt.u32.u64 %0, t; }" : "=r"(a) : "l"(p)); return a;
}
__device__ __forceinline__ uint pk(float lo, float hi) {   // low bf16 <- lo
    uint r; asm("cvt.rn.bf16x2.f32 %0, %1, %2;" : "=r"(r) : "f"(hi), "f"(lo)); return r;
}
__device__ __forceinline__ float bflo(uint u) { return __uint_as_float(u << 16); }
__device__ __forceinline__ float bfhi(uint u) { return __uint_as_float(u & 0xffff0000u); }
__device__ __forceinline__ float sqa(float x) { float r; asm("sqrt.approx.f32 %0, %1;" : "=f"(r) : "f"(x)); return r; }
__device__ __forceinline__ float en(float x) {  // e^-x
    float r; asm("mul.f32 %0, %1, 0fBFB8AA3B;\n\tex2.approx.f32 %0, %0;" : "=f"(r) : "f"(x)); return r;
}
__device__ __forceinline__ void ldsm2(uint* b, uint a) {
    asm volatile("ldmatrix.sync.aligned.m8n8.x2.shared.b16 {%0,%1},[%2];" : "=r"(b[0]), "=r"(b[1]) : "r"(a));
}
__device__ __forceinline__ void ldsm2t(uint* b, uint a) {
    asm volatile("ldmatrix.sync.aligned.m8n8.x2.trans.shared.b16 {%0,%1},[%2];" : "=r"(b[0]), "=r"(b[1]) : "r"(a));
}
__device__ __forceinline__ void ldsm4(uint* r, uint a) {
    asm volatile("ldmatrix.sync.aligned.m8n8.x4.shared.b16 {%0,%1,%2,%3},[%4];"
                 : "=r"(r[0]), "=r"(r[1]), "=r"(r[2]), "=r"(r[3]) : "r"(a));
}
__device__ __forceinline__ void mma(float* c, const uint* a, const uint* b) {
    asm volatile("mma.sync.aligned.m16n8k16.row.col.f32.bf16.bf16.f32 "
                 "{%0,%1,%2,%3},{%4,%5,%6,%7},{%8,%9},{%0,%1,%2,%3};"
                 : "+f"(c[0]), "+f"(c[1]), "+f"(c[2]), "+f"(c[3])
                 : "r"(a[0]), "r"(a[1]), "r"(a[2]), "r"(a[3]), "r"(b[0]), "r"(b[1]));
}

// exact rescan: reference rule (seq dot, ref-order d2, rn-sqrt, first index of min)
__device__ int rescan(int n, int l, const float* __restrict__ z,
                      const float* __restrict__ codes, const float* __restrict__ w2s) {
    int lane = threadIdx.x & 31;
    float h[16];
    const float* zp = z + (size_t)(n >> 10) * 131072 + (size_t)(l * 16) * 1024 + (n & 1023);
    #pragma unroll
    for (int d = 0; d < 16; d++) h[d] = zp[(size_t)d * 1024];
    float h2 = 0.f;
    #pragma unroll
    for (int d = 0; d < 16; d++) h2 = __fadd_rn(h2, __fmul_rn(h[d], h[d]));
    const float* cb = codes + ((size_t)l * KN + lane * 16) * 16;
    float sm = 3.4e38f; int km = lane * 16;
    for (int i = 0; i < 16; i++) {
        float dot = 0.f;
        #pragma unroll
        for (int d = 0; d < 16; d++) dot = fmaf(h[d], cb[i * 16 + d], dot);
        float d2 = __fadd_rn(fmaf(-2.f, dot, h2), w2s[lane * 16 + i]);
        float sd = __fsqrt_rn(fmaxf(d2, 1e-12f));
        if (sd < sm) { sm = sd; km = lane * 16 + i; }
    }
    #pragma unroll
    for (int off = 16; off; off >>= 1) {
        float os = __shfl_xor_sync(~0u, sm, off);
        int   ok = __shfl_xor_sync(~0u, km, off);
        if (os < sm || (os == sm && ok < km)) { sm = os; km = ok; }
    }
    return km;
}

__global__ __launch_bounds__(128, 4)
void vq_kernel(const float* __restrict__ z, const float* __restrict__ codes,
               float* __restrict__ out, int out_size)
{
    __shared__ unsigned short chs[KN * 16], cls[KN * 16];   // codes bf16 hi/lo [k][d]
    __shared__ float w2s[KN];
    __shared__ unsigned short sh[4][256], sl[4][256];       // h tile per warp [16][16]
    __shared__ float h2s[4][16];

    const int l = blockIdx.y, tid = threadIdx.x, w = tid >> 5, lane = tid & 31;
    const int q = lane & 3, r4 = lane >> 2;

    for (int r = tid; r < KN; r += 128) {
        float v[16];
        const float4* cr = (const float4*)(codes + ((size_t)l * KN + r) * 16);
        #pragma unroll
        for (int j = 0; j < 4; j++) { float4 t = cr[j]; v[4*j]=t.x; v[4*j+1]=t.y; v[4*j+2]=t.z; v[4*j+3]=t.w; }
        float s = 0.f;
        #pragma unroll
        for (int d = 0; d < 16; d++) s = __fadd_rn(s, __fmul_rn(v[d], v[d]));
        w2s[r] = s;
        #pragma unroll
        for (int j = 0; j < 8; j++) {
            uint uh = pk(v[2*j], v[2*j+1]);
            uint ul = pk(v[2*j] - bflo(uh), v[2*j+1] - bfhi(uh));
            ((uint*)chs)[r * 8 + j] = uh; ((uint*)cls)[r * 8 + j] = ul;
        }
    }
    __syncthreads();

    const uint chb = s2u(chs), clb = s2u(cls), shb = s2u(sh[w]), slb = s2u(sl[w]);
    const int ln15 = lane & 15;
    const uint offA  = (uint)((lane & 15) * 32 + (lane >> 4) * 16);
    const uint offG1 = (uint)((ln15 & 7) * 32 + (ln15 >> 3) * 16);
    const uint offG2 = (uint)(ln15 * 32);

    for (int tile = blockIdx.x * 16 + w * 4, te = tile + 4; tile < te; tile++) {
        {   // stage h (pos = lane>>1, d-half = lane&1) + exact ref-order h2
            int pos = lane >> 1, hf = lane & 1, n = tile * 16 + pos;
            const float* zp = z + (size_t)(n >> 10) * 131072 + (size_t)(l * 16 + hf * 8) * 1024 + (n & 1023);
            float v[8];
            #pragma unroll
            for (int i = 0; i < 8; i++) v[i] = zp[(size_t)i * 1024];
            float p = 0.f;
            #pragma unroll
            for (int i = 0; i < 8; i++) p = __fadd_rn(p, __fmul_rn(v[i], v[i]));
            float pe = __shfl_xor_sync(~0u, p, 1);
            if (hf) {
                float h2 = pe;
                #pragma unroll
                for (int i = 0; i < 8; i++) h2 = __fadd_rn(h2, __fmul_rn(v[i], v[i]));
                h2s[w][pos] = h2;
            }
            #pragma unroll
            for (int j = 0; j < 4; j++) {
                uint uh = pk(v[2*j], v[2*j+1]);
                uint ul = pk(v[2*j] - bflo(uh), v[2*j+1] - bfhi(uh));
                ((uint*)sh[w])[pos * 8 + hf * 4 + j] = uh;
                ((uint*)sl[w])[pos * 8 + hf * 4 + j] = ul;
            }
        }
        __syncwarp();
        uint ah[4], al[4];
        ldsm4(ah, shb + offA); ldsm4(al, slb + offA);
        float h2A = h2s[w][r4], h2B = h2s[w][r4 + 8];

        float o0[4] = {0,0,0,0}, o1[4] = {0,0,0,0};
        float sA = 0.f, sB = 0.f, b0A = 3.4e38f, b1A = 3.4e38f, b0B = 3.4e38f, b1B = 3.4e38f;
        int k0A = 0, k0B = 0;

        for (int kc = 0; kc < KN; kc += 16) {
            uint bh[2], bl[2];
            float t0[4] = {0,0,0,0}, t1[4] = {0,0,0,0};
            ldsm2(bh, chb + offG1 + kc * 32); ldsm2(bl, clb + offG1 + kc * 32);
            mma(t0, ah, bh); mma(t0, ah, bl); mma(t0, al, bh);
            ldsm2(bh, chb + offG1 + kc * 32 + 256); ldsm2(bl, clb + offG1 + kc * 32 + 256);
            mma(t1, ah, bh); mma(t1, ah, bl); mma(t1, al, bh);

            float w20 = w2s[kc+2*q], w21 = w2s[kc+2*q+1], w22 = w2s[kc+8+2*q], w23 = w2s[kc+8+2*q+1];
            float vA[4] = { fmaf(-2.f,t0[0],h2A+w20), fmaf(-2.f,t0[1],h2A+w21),
                            fmaf(-2.f,t1[0],h2A+w22), fmaf(-2.f,t1[1],h2A+w23) };
            float vB[4] = { fmaf(-2.f,t0[2],h2B+w20), fmaf(-2.f,t0[3],h2B+w21),
                            fmaf(-2.f,t1[2],h2B+w22), fmaf(-2.f,t1[3],h2B+w23) };
            int kk[4] = { kc+2*q, kc+2*q+1, kc+8+2*q, kc+8+2*q+1 };
            float wA[4], wB[4];
            #pragma unroll
            for (int i = 0; i < 4; i++) {
                if (vA[i] < b0A) { b1A = b0A; b0A = vA[i]; k0A = kk[i]; } else b1A = fminf(b1A, vA[i]);
                if (vB[i] < b0B) { b1B = b0B; b0B = vB[i]; k0B = kk[i]; } else b1B = fminf(b1B, vB[i]);
                wA[i] = en(sqa(fmaxf(vA[i], 1e-12f)));
                wB[i] = en(sqa(fmaxf(vB[i], 1e-12f)));
                sA += wA[i]; sB += wB[i];
            }
            uint ph[4] = { pk(wA[0],wA[1]), pk(wB[0],wB[1]), pk(wA[2],wA[3]), pk(wB[2],wB[3]) };
            uint pl[4] = { pk(wA[0]-bflo(ph[0]), wA[1]-bfhi(ph[0])),
                           pk(wB[0]-bflo(ph[1]), wB[1]-bfhi(ph[1])),
                           pk(wA[2]-bflo(ph[2]), wA[3]-bfhi(ph[2])),
                           pk(wB[2]-bflo(ph[3]), wB[3]-bfhi(ph[3])) };
            ldsm2t(bh, chb + offG2 + kc * 32); ldsm2t(bl, clb + offG2 + kc * 32);
            mma(o0, ph, bh); mma(o0, ph, bl); mma(o0, pl, bh);
            ldsm2t(bh, chb + offG2 + kc * 32 + 16); ldsm2t(bl, clb + offG2 + kc * 32 + 16);
            mma(o1, ph, bh); mma(o1, ph, bl); mma(o1, pl, bh);
        }

        #pragma unroll
        for (int off = 1; off <= 2; off <<= 1) {
            sA += __shfl_xor_sync(~0u, sA, off);
            sB += __shfl_xor_sync(~0u, sB, off);
            float oa0 = __shfl_xor_sync(~0u, b0A, off), oa1 = __shfl_xor_sync(~0u, b1A, off);
            int oka = __shfl_xor_sync(~0u, k0A, off);
            b1A = fminf(fminf(b1A, oa1), fmaxf(b0A, oa0));
            if (oa0 < b0A || (oa0 == b0A && oka < k0A)) { b0A = oa0; k0A = oka; }
            float ob0 = __shfl_xor_sync(~0u, b0B, off), ob1 = __shfl_xor_sync(~0u, b1B, off);
            int okb = __shfl_xor_sync(~0u, k0B, off);
            b1B = fminf(fminf(b1B, ob1), fmaxf(b0B, ob0));
            if (ob0 < b0B || (ob0 == b0B && okb < k0B)) { b0B = ob0; k0B = okb; }
        }

        uint mA = __ballot_sync(~0u, b1A - b0A < GUARD);
        uint mB = __ballot_sync(~0u, b1B - b0B < GUARD);
        int bkA = k0A, bkB = k0B;
        for (int r = 0; r < 8; r++) {
            if ((mA >> (4 * r)) & 1) { int bk = rescan(tile*16 + r, l, z, codes, w2s);     if (r4 == r) bkA = bk; }
            if ((mB >> (4 * r)) & 1) { int bk = rescan(tile*16 + 8 + r, l, z, codes, w2s); if (r4 == r) bkB = bk; }
        }

        int nA = tile * 16 + r4, nB = nA + 8;
        float ivA = 1.f / sA, ivB = 1.f / sB;
        size_t bA = (size_t)nA * 128 + l * 16, bB = (size_t)nB * 128 + l * 16;
        *(float2*)(out + bA + 2*q)     = make_float2(o0[0]*ivA, o0[1]*ivA);
        *(float2*)(out + bA + 8 + 2*q) = make_float2(o1[0]*ivA, o1[1]*ivA);
        *(float2*)(out + bB + 2*q)     = make_float2(o0[2]*ivB, o0[3]*ivB);
        *(float2*)(out + bB + 8 + 2*q) = make_float2(o1[2]*ivB, o1[3]*ivB);
        if (out_size >= 2 * HN) {
            const float4* ca = (const float4*)(codes + ((size_t)l * KN + bkA) * 16);
            const float4* cb = (const float4*)(codes + ((size_t)l * KN + bkB) * 16);
            ((float4*)(out + HN + bA))[q] = ca[q];
            ((float4*)(out + HN + bB))[q] = cb[q];
        }
        if (q == 0 && out_size >= 2 * HN + NPOS * LN) {
            out[2 * HN + (size_t)nA * 8 + l] = (float)bkA;
            out[2 * HN + (size_t)nB * 8 + l] = (float)bkB;
        }
        __syncwarp();
    }
}

extern "C" void kernel_launch(void* const* d_in, const int* in_sizes, int n_in,
                              void* d_out, int out_size) {
    vq_kernel<<<dim3(64, LN), 128>>>((const float*)d_in[0], (const float*)d_in[1],
                                     (float*)d_out, out_size);
}

// round 17
// speedup vs baseline: 1.2283x; 1.1061x over previous
#include <cuda_runtime.h>
#include <cstdint>

#define KN   512
#define LN   8
#define NPOS 16384
#define HN   (NPOS * 128)
#define GUARD 2e-3f
#define NBX  74                 // blocks per l; 148 SMs x 4 CTAs = 592 = 74*8
typedef unsigned int uint;

__device__ __forceinline__ uint s2u(const void* p) {
    uint a; asm("{ .reg .u64 t; cvta.to.shared.u64 t, %1; cvt.u32.u64 %0, t; }" : "=r"(a) : "l"(p)); return a;
}
__device__ __forceinline__ uint pk(float lo, float hi) {   // low bf16 <- lo
    uint r; asm("cvt.rn.bf16x2.f32 %0, %1, %2;" : "=r"(r) : "f"(hi), "f"(lo)); return r;
}
__device__ __forceinline__ float bflo(uint u) { return __uint_as_float(u << 16); }
__device__ __forceinline__ float bfhi(uint u) { return __uint_as_float(u & 0xffff0000u); }
__device__ __forceinline__ float sqa(float x) { float r; asm("sqrt.approx.f32 %0, %1;" : "=f"(r) : "f"(x)); return r; }
__device__ __forceinline__ float en(float x) {  // e^-x
    float r; asm("mul.f32 %0, %1, 0fBFB8AA3B;\n\tex2.approx.f32 %0, %0;" : "=f"(r) : "f"(x)); return r;
}
__device__ __forceinline__ void ldsm2(uint* b, uint a) {
    asm volatile("ldmatrix.sync.aligned.m8n8.x2.shared.b16 {%0,%1},[%2];" : "=r"(b[0]), "=r"(b[1]) : "r"(a));
}
__device__ __forceinline__ void ldsm2t(uint* b, uint a) {
    asm volatile("ldmatrix.sync.aligned.m8n8.x2.trans.shared.b16 {%0,%1},[%2];" : "=r"(b[0]), "=r"(b[1]) : "r"(a));
}
__device__ __forceinline__ void ldsm4(uint* r, uint a) {
    asm volatile("ldmatrix.sync.aligned.m8n8.x4.shared.b16 {%0,%1,%2,%3},[%4];"
                 : "=r"(r[0]), "=r"(r[1]), "=r"(r[2]), "=r"(r[3]) : "r"(a));
}
__device__ __forceinline__ void mma(float* c, const uint* a, const uint* b) {
    asm volatile("mma.sync.aligned.m16n8k16.row.col.f32.bf16.bf16.f32 "
                 "{%0,%1,%2,%3},{%4,%5,%6,%7},{%8,%9},{%0,%1,%2,%3};"
                 : "+f"(c[0]), "+f"(c[1]), "+f"(c[2]), "+f"(c[3])
                 : "r"(a[0]), "r"(a[1]), "r"(a[2]), "r"(a[3]), "r"(b[0]), "r"(b[1]));
}

// exact rescan: reference rule (seq dot, ref-order d2, rn-sqrt, first index of min)
__device__ int rescan(int n, int l, const float* __restrict__ z,
                      const float* __restrict__ codes, const float* __restrict__ w2s) {
    int lane = threadIdx.x & 31;
    float h[16];
    const float* zp = z + (size_t)(n >> 10) * 131072 + (size_t)(l * 16) * 1024 + (n & 1023);
    #pragma unroll
    for (int d = 0; d < 16; d++) h[d] = zp[(size_t)d * 1024];
    float h2 = 0.f;
    #pragma unroll
    for (int d = 0; d < 16; d++) h2 = __fadd_rn(h2, __fmul_rn(h[d], h[d]));
    const float* cb = codes + ((size_t)l * KN + lane * 16) * 16;
    float sm = 3.4e38f; int km = lane * 16;
    for (int i = 0; i < 16; i++) {
        float dot = 0.f;
        #pragma unroll
        for (int d = 0; d < 16; d++) dot = fmaf(h[d], cb[i * 16 + d], dot);
        float d2 = __fadd_rn(fmaf(-2.f, dot, h2), w2s[lane * 16 + i]);
        float sd = __fsqrt_rn(fmaxf(d2, 1e-12f));
        if (sd < sm) { sm = sd; km = lane * 16 + i; }
    }
    #pragma unroll
    for (int off = 16; off; off >>= 1) {
        float os = __shfl_xor_sync(~0u, sm, off);
        int   ok = __shfl_xor_sync(~0u, km, off);
        if (os < sm || (os == sm && ok < km)) { sm = os; km = ok; }
    }
    return km;
}

__global__ __launch_bounds__(128, 4)
void vq_kernel(const float* __restrict__ z, const float* __restrict__ codes,
               float* __restrict__ out, int out_size)
{
    __shared__ unsigned short chs[KN * 16], cls[KN * 16];   // codes bf16 hi/lo [k][d]
    __shared__ float w2s[KN];
    __shared__ unsigned short sh[4][256], sl[4][256];       // h tile per warp [16][16]
    __shared__ float h2s[4][16];

    const int l = blockIdx.y, tid = threadIdx.x, w = tid >> 5, lane = tid & 31;
    const int q = lane & 3, r4 = lane >> 2;

    for (int r = tid; r < KN; r += 128) {
        float v[16];
        const float4* cr = (const float4*)(codes + ((size_t)l * KN + r) * 16);
        #pragma unroll
        for (int j = 0; j < 4; j++) { float4 t = cr[j]; v[4*j]=t.x; v[4*j+1]=t.y; v[4*j+2]=t.z; v[4*j+3]=t.w; }
        float s = 0.f;
        #pragma unroll
        for (int d = 0; d < 16; d++) s = __fadd_rn(s, __fmul_rn(v[d], v[d]));
        w2s[r] = s;
        #pragma unroll
        for (int j = 0; j < 8; j++) {
            uint uh = pk(v[2*j], v[2*j+1]);
            uint ul = pk(v[2*j] - bflo(uh), v[2*j+1] - bfhi(uh));
            ((uint*)chs)[r * 8 + j] = uh; ((uint*)cls)[r * 8 + j] = ul;
        }
    }
    __syncthreads();

    const uint chb = s2u(chs), clb = s2u(cls), shb = s2u(sh[w]), slb = s2u(sl[w]);
    const int ln15 = lane & 15;
    const uint offA  = (uint)((lane & 15) * 32 + (lane >> 4) * 16);
    const uint offG1 = (uint)((ln15 & 7) * 32 + (ln15 >> 3) * 16);
    const uint offG2 = (uint)(ln15 * 32);

    // balanced tile partition: 1024 tiles per l over NBX blocks (13-14 each),
    // warps round-robin within the block -> every SM carries exactly 4 CTAs.
    const int tstart = (1024 * blockIdx.x) / NBX;
    const int tend   = (1024 * (blockIdx.x + 1)) / NBX;

    for (int tile = tstart + w; tile < tend; tile += 4) {
        {   // stage h (pos = lane>>1, d-half = lane&1) + exact ref-order h2
            int pos = lane >> 1, hf = lane & 1, n = tile * 16 + pos;
            const float* zp = z + (size_t)(n >> 10) * 131072 + (size_t)(l * 16 + hf * 8) * 1024 + (n & 1023);
            float v[8];
            #pragma unroll
            for (int i = 0; i < 8; i++) v[i] = zp[(size_t)i * 1024];
            float p = 0.f;
            #pragma unroll
            for (int i = 0; i < 8; i++) p = __fadd_rn(p, __fmul_rn(v[i], v[i]));
            float pe = __shfl_xor_sync(~0u, p, 1);
            if (hf) {
                float h2 = pe;
                #pragma unroll
                for (int i = 0; i < 8; i++) h2 = __fadd_rn(h2, __fmul_rn(v[i], v[i]));
                h2s[w][pos] = h2;
            }
            #pragma unroll
            for (int j = 0; j < 4; j++) {
                uint uh = pk(v[2*j], v[2*j+1]);
                uint ul = pk(v[2*j] - bflo(uh), v[2*j+1] - bfhi(uh));
                ((uint*)sh[w])[pos * 8 + hf * 4 + j] = uh;
                ((uint*)sl[w])[pos * 8 + hf * 4 + j] = ul;
            }
        }
        __syncwarp();
        uint ah[4], al[4];
        ldsm4(ah, shb + offA); ldsm4(al, slb + offA);
        float h2A = h2s[w][r4], h2B = h2s[w][r4 + 8];

        float o0[4] = {0,0,0,0}, o1[4] = {0,0,0,0};
        float sA = 0.f, sB = 0.f, b0A = 3.4e38f, b1A = 3.4e38f, b0B = 3.4e38f, b1B = 3.4e38f;
        int k0A = 0, k0B = 0;

        for (int kc = 0; kc < KN; kc += 16) {
            uint bh[2], bl[2];
            float t0[4] = {0,0,0,0}, t1[4] = {0,0,0,0};
            ldsm2(bh, chb + offG1 + kc * 32); ldsm2(bl, clb + offG1 + kc * 32);
            mma(t0, ah, bh); mma(t0, ah, bl); mma(t0, al, bh);
            ldsm2(bh, chb + offG1 + kc * 32 + 256); ldsm2(bl, clb + offG1 + kc * 32 + 256);
            mma(t1, ah, bh); mma(t1, ah, bl); mma(t1, al, bh);

            float w20 = w2s[kc+2*q], w21 = w2s[kc+2*q+1], w22 = w2s[kc+8+2*q], w23 = w2s[kc+8+2*q+1];
            float vA[4] = { fmaf(-2.f,t0[0],h2A+w20), fmaf(-2.f,t0[1],h2A+w21),
                            fmaf(-2.f,t1[0],h2A+w22), fmaf(-2.f,t1[1],h2A+w23) };
            float vB[4] = { fmaf(-2.f,t0[2],h2B+w20), fmaf(-2.f,t0[3],h2B+w21),
                            fmaf(-2.f,t1[2],h2B+w22), fmaf(-2.f,t1[3],h2B+w23) };
            int kk[4] = { kc+2*q, kc+2*q+1, kc+8+2*q, kc+8+2*q+1 };
            float wA[4], wB[4];
            #pragma unroll
            for (int i = 0; i < 4; i++) {
                if (vA[i] < b0A) { b1A = b0A; b0A = vA[i]; k0A = kk[i]; } else b1A = fminf(b1A, vA[i]);
                if (vB[i] < b0B) { b1B = b0B; b0B = vB[i]; k0B = kk[i]; } else b1B = fminf(b1B, vB[i]);
                wA[i] = en(sqa(fmaxf(vA[i], 1e-12f)));
                wB[i] = en(sqa(fmaxf(vB[i], 1e-12f)));
                sA += wA[i]; sB += wB[i];
            }
            uint ph[4] = { pk(wA[0],wA[1]), pk(wB[0],wB[1]), pk(wA[2],wA[3]), pk(wB[2],wB[3]) };
            uint pl[4] = { pk(wA[0]-bflo(ph[0]), wA[1]-bfhi(ph[0])),
                           pk(wB[0]-bflo(ph[1]), wB[1]-bfhi(ph[1])),
                           pk(wA[2]-bflo(ph[2]), wA[3]-bfhi(ph[2])),
                           pk(wB[2]-bflo(ph[3]), wB[3]-bfhi(ph[3])) };
            ldsm2t(bh, chb + offG2 + kc * 32); ldsm2t(bl, clb + offG2 + kc * 32);
            mma(o0, ph, bh); mma(o0, ph, bl); mma(o0, pl, bh);
            ldsm2t(bh, chb + offG2 + kc * 32 + 16); ldsm2t(bl, clb + offG2 + kc * 32 + 16);
            mma(o1, ph, bh); mma(o1, ph, bl); mma(o1, pl, bh);
        }

        #pragma unroll
        for (int off = 1; off <= 2; off <<= 1) {
            sA += __shfl_xor_sync(~0u, sA, off);
            sB += __shfl_xor_sync(~0u, sB, off);
            float oa0 = __shfl_xor_sync(~0u, b0A, off), oa1 = __shfl_xor_sync(~0u, b1A, off);
            int oka = __shfl_xor_sync(~0u, k0A, off);
            b1A = fminf(fminf(b1A, oa1), fmaxf(b0A, oa0));
            if (oa0 < b0A || (oa0 == b0A && oka < k0A)) { b0A = oa0; k0A = oka; }
            float ob0 = __shfl_xor_sync(~0u, b0B, off), ob1 = __shfl_xor_sync(~0u, b1B, off);
            int okb = __shfl_xor_sync(~0u, k0B, off);
            b1B = fminf(fminf(b1B, ob1), fmaxf(b0B, ob0));
            if (ob0 < b0B || (ob0 == b0B && okb < k0B)) { b0B = ob0; k0B = okb; }
        }

        uint mA = __ballot_sync(~0u, b1A - b0A < GUARD);
        uint mB = __ballot_sync(~0u, b1B - b0B < GUARD);
        int bkA = k0A, bkB = k0B;
        for (int r = 0; r < 8; r++) {
            if ((mA >> (4 * r)) & 1) { int bk = rescan(tile*16 + r, l, z, codes, w2s);     if (r4 == r) bkA = bk; }
            if ((mB >> (4 * r)) & 1) { int bk = rescan(tile*16 + 8 + r, l, z, codes, w2s); if (r4 == r) bkB = bk; }
        }

        int nA = tile * 16 + r4, nB = nA + 8;
        float ivA = 1.f / sA, ivB = 1.f / sB;
        size_t bA = (size_t)nA * 128 + l * 16, bB = (size_t)nB * 128 + l * 16;
        *(float2*)(out + bA + 2*q)     = make_float2(o0[0]*ivA, o0[1]*ivA);
        *(float2*)(out + bA + 8 + 2*q) = make_float2(o1[0]*ivA, o1[1]*ivA);
        *(float2*)(out + bB + 2*q)     = make_float2(o0[2]*ivB, o0[3]*ivB);
        *(float2*)(out + bB + 8 + 2*q) = make_float2(o1[2]*ivB, o1[3]*ivB);
        if (out_size >= 2 * HN) {
            const float4* ca = (const float4*)(codes + ((size_t)l * KN + bkA) * 16);
            const float4* cb = (const float4*)(codes + ((size_t)l * KN + bkB) * 16);
            ((float4*)(out + HN + bA))[q] = ca[q];
            ((float4*)(out + HN + bB))[q] = cb[q];
        }
        if (q == 0 && out_size >= 2 * HN + NPOS * LN) {
            out[2 * HN + (size_t)nA * 8 + l] = (float)bkA;
            out[2 * HN + (size_t)nB * 8 + l] = (float)bkB;
        }
        __syncwarp();
    }
}

extern "C" void kernel_launch(void* const* d_in, const int* in_sizes, int n_in,
                              void* d_out, int out_size) {
    vq_kernel<<<dim3(NBX, LN), 128>>>((const float*)d_in[0], (const float*)d_in[1],
                                      (float*)d_out, out_size);
}